// round 1
// baseline (speedup 1.0000x reference)
#include <cuda_runtime.h>
#include <math.h>

#define B0 32
#define C0 512
#define HW 4096
#define DC 32
#define NS 16
#define RK 32
#define LL 512

// ---- global scratch (static device allocations; no runtime malloc) ----
__device__ float g_avg[B0 * C0];
__device__ float g_mx[B0 * C0];
__device__ float g_U[B0 * 2 * DC * LL];      // u = xk, layout [bk*32+d][l]
__device__ float g_Delta[B0 * 2 * DC * LL];  // post-softplus delta, same layout
__device__ float g_Bs[B0 * 2 * LL * NS];     // [bk][l][n]
__device__ float g_Cs[B0 * 2 * LL * NS];     // [bk][l][n]
__device__ float g_Y[B0 * 2 * DC * LL];      // scan output, [bk*32+d][l]
__device__ float g_attn[B0 * C0];

__device__ __forceinline__ float gelu_exact(float v) {
    return 0.5f * v * (1.0f + erff(v * 0.70710678118654752f));
}

// ============================================================
// K1: avg + max pool over H*W per (b,c).  256 MB read, HBM-bound.
// ============================================================
__global__ void pool_kernel(const float* __restrict__ x) {
    int bc = blockIdx.x;
    const float4* xp = (const float4*)(x + (size_t)bc * HW);
    float s = 0.0f, m = -INFINITY;
#pragma unroll
    for (int it = 0; it < 4; it++) {
        int i = it * 256 + threadIdx.x;
        float4 v = xp[i];
        s += (v.x + v.y) + (v.z + v.w);
        m = fmaxf(m, fmaxf(fmaxf(v.x, v.y), fmaxf(v.z, v.w)));
    }
#pragma unroll
    for (int o = 16; o; o >>= 1) {
        s += __shfl_xor_sync(0xffffffffu, s, o);
        m = fmaxf(m, __shfl_xor_sync(0xffffffffu, m, o));
    }
    __shared__ float ss[8], sm[8];
    int w = threadIdx.x >> 5;
    if ((threadIdx.x & 31) == 0) { ss[w] = s; sm[w] = m; }
    __syncthreads();
    if (threadIdx.x == 0) {
        float S = ss[0], M = sm[0];
#pragma unroll
        for (int i = 1; i < 8; i++) { S += ss[i]; M = fmaxf(M, sm[i]); }
        g_avg[bc] = S * (1.0f / (float)HW);
        g_mx[bc] = M;
    }
}

// ============================================================
// K2: per (b,k,l): u (gelu(BN(w_cin . xsc))), projections to
//     dts_raw -> delta(softplus), Bs, Cs.  ~100M MACs total.
//     grid = B0*2*4 blocks of 128 threads (thread == one l).
// ============================================================
__global__ void prep_kernel(const float* __restrict__ xc_w,
                            const float* __restrict__ dtc_w,
                            const float* __restrict__ dtc_b,
                            const float* __restrict__ w_cin,
                            const float* __restrict__ bn_g,
                            const float* __restrict__ bn_b,
                            const float* __restrict__ bn_m,
                            const float* __restrict__ bn_v) {
    const int bk = blockIdx.x >> 2;        // 0..63
    const int b = bk >> 1, k = bk & 1;
    const int l = ((blockIdx.x & 3) << 7) + threadIdx.x;  // 0..511

    __shared__ float sWp[64 * 32];
    __shared__ float sW2[32 * 32];
    __shared__ float sAvg[512], sMx[512];
    __shared__ float sCin0[32], sCin1[32], sScale[32], sShift[32], sBias[32];

    for (int i = threadIdx.x; i < 64 * 32; i += 128) sWp[i] = xc_w[k * 2048 + i];
    for (int i = threadIdx.x; i < 32 * 32; i += 128) sW2[i] = dtc_w[k * 1024 + i];
    for (int i = threadIdx.x; i < 512; i += 128) {
        sAvg[i] = g_avg[b * 512 + i];
        sMx[i] = g_mx[b * 512 + i];
    }
    if (threadIdx.x < 32) {
        int d = threadIdx.x;
        sCin0[d] = w_cin[d * 2 + 0];
        sCin1[d] = w_cin[d * 2 + 1];
        float sc = rsqrtf(bn_v[d] + 1e-5f) * bn_g[d];
        sScale[d] = sc;
        sShift[d] = bn_b[d] - bn_m[d] * sc;
        sBias[d] = dtc_b[k * 32 + d];
    }
    __syncthreads();

    const int c = (k == 0) ? l : (511 - l);
    const float av = sAvg[c], mv = sMx[c];

    float u[32];
#pragma unroll
    for (int d = 0; d < 32; d++) {
        float v = sCin0[d] * av + sCin1[d] * mv;
        v = v * sScale[d] + sShift[d];
        v = gelu_exact(v);
        u[d] = v;
        g_U[(bk * 32 + d) * LL + l] = v;
    }

    float dts[32];
#pragma unroll
    for (int c2 = 0; c2 < 32; c2++) {
        float a = 0.0f;
#pragma unroll
        for (int d = 0; d < 32; d++) a += u[d] * sWp[c2 * 32 + d];
        dts[c2] = a;
    }
#pragma unroll
    for (int n = 0; n < 16; n++) {
        float ba = 0.0f, ca = 0.0f;
#pragma unroll
        for (int d = 0; d < 32; d++) {
            ba += u[d] * sWp[(32 + n) * 32 + d];
            ca += u[d] * sWp[(48 + n) * 32 + d];
        }
        g_Bs[(bk * 512 + l) * NS + n] = ba;
        g_Cs[(bk * 512 + l) * NS + n] = ca;
    }
#pragma unroll
    for (int d = 0; d < 32; d++) {
        float a = sBias[d];
#pragma unroll
        for (int r = 0; r < 32; r++) a += dts[r] * sW2[d * 32 + r];
        // stable softplus
        float sp = fmaxf(a, 0.0f) + log1pf(__expf(-fabsf(a)));
        g_Delta[(bk * 32 + d) * LL + l] = sp;
    }
}

// ============================================================
// K3: selective scan. One warp = two (b,k,d) lanes; within each
//     16-lane half, lane n owns state n. 2048 scan lanes total.
//     grid = 256 blocks x 128 threads.
// ============================================================
__global__ void scan_kernel(const float* __restrict__ Ac_logs,
                            const float* __restrict__ Dcs) {
    const int warp = threadIdx.x >> 5;
    const int lane = threadIdx.x & 31;
    const int half = lane >> 4;
    const int n = lane & 15;
    const int g = blockIdx.x * 8 + warp * 2 + half;  // 0..2047
    const int kd = g & 63;
    const int bkn = g >> 5;  // (b,k) index

    const float* __restrict__ dp = g_Delta + (size_t)g * LL;
    const float* __restrict__ up = g_U + (size_t)g * LL;
    const float* __restrict__ Bp = g_Bs + (size_t)bkn * (LL * NS);
    const float* __restrict__ Cp = g_Cs + (size_t)bkn * (LL * NS);
    float* __restrict__ yp = g_Y + (size_t)g * LL;

    const float A = -__expf(Ac_logs[kd * NS + n]);
    const float cA = A * 1.4426950408889634f;  // for exp2f
    const float Dv = Dcs[kd];

    float h = 0.0f;
    for (int l4 = 0; l4 < LL / 4; l4++) {
        const float4 dl4 = *(const float4*)(dp + l4 * 4);
        const float4 ul4 = *(const float4*)(up + l4 * 4);
        const float dl[4] = {dl4.x, dl4.y, dl4.z, dl4.w};
        const float ul[4] = {ul4.x, ul4.y, ul4.z, ul4.w};
        float yv[4];
#pragma unroll
        for (int j = 0; j < 4; j++) {
            const int l = l4 * 4 + j;
            const float delta = dl[j];
            const float uu = ul[j];
            const float Bv = Bp[l * NS + n];
            const float Cv = Cp[l * NS + n];
            const float dA = exp2f(delta * cA);
            h = fmaf(dA, h, (delta * uu) * Bv);
            float p = h * Cv;
            p += __shfl_xor_sync(0xffffffffu, p, 1);
            p += __shfl_xor_sync(0xffffffffu, p, 2);
            p += __shfl_xor_sync(0xffffffffu, p, 4);
            p += __shfl_xor_sync(0xffffffffu, p, 8);
            yv[j] = p + Dv * uu;
        }
        if (n == 0) *(float4*)(yp + l4 * 4) = make_float4(yv[0], yv[1], yv[2], yv[3]);
    }
}

// ============================================================
// K4: combine directions, dot with w_cout, gelu, LayerNorm over L.
//     grid = B0 blocks x 512 threads (thread == l).
// ============================================================
__global__ void combine_ln_kernel(const float* __restrict__ w_cout,
                                  const float* __restrict__ ln_g,
                                  const float* __restrict__ ln_b) {
    const int b = blockIdx.x;
    const int l = threadIdx.x;
    __shared__ float sw[32];
    if (l < 32) sw[l] = w_cout[l];
    __syncthreads();

    const float* __restrict__ y0 = g_Y + (size_t)b * 64 * LL;
    const float* __restrict__ y1 = y0 + 32 * LL;
    float acc = 0.0f;
#pragma unroll
    for (int d = 0; d < 32; d++)
        acc += (y0[d * LL + l] + y1[d * LL + (511 - l)]) * sw[d];
    const float yb = gelu_exact(acc);

    float s = yb, s2 = yb * yb;
#pragma unroll
    for (int o = 16; o; o >>= 1) {
        s += __shfl_xor_sync(0xffffffffu, s, o);
        s2 += __shfl_xor_sync(0xffffffffu, s2, o);
    }
    __shared__ float rs[16], rs2[16];
    __shared__ float smu, srv;
    const int w = l >> 5;
    if ((l & 31) == 0) { rs[w] = s; rs2[w] = s2; }
    __syncthreads();
    if (l == 0) {
        float S = 0.0f, S2 = 0.0f;
#pragma unroll
        for (int i = 0; i < 16; i++) { S += rs[i]; S2 += rs2[i]; }
        float mu = S * (1.0f / 512.0f);
        float var = S2 * (1.0f / 512.0f) - mu * mu;
        smu = mu;
        srv = rsqrtf(var + 1e-5f);
    }
    __syncthreads();
    g_attn[b * 512 + l] = (yb - smu) * srv * ln_g[l] + ln_b[l];
}

// ============================================================
// K5: out = x * (1 + attn[b,c]).  512 MB traffic, HBM-bound.
// ============================================================
__global__ void out_kernel(const float* __restrict__ x, float* __restrict__ out) {
    const size_t i = (size_t)blockIdx.x * blockDim.x + threadIdx.x;  // float4 index
    const int bc = (int)(i >> 10);  // 1024 float4 per (b,c)
    const float a = 1.0f + g_attn[bc];
    float4 v = ((const float4*)x)[i];
    v.x *= a; v.y *= a; v.z *= a; v.w *= a;
    ((float4*)out)[i] = v;
}

extern "C" void kernel_launch(void* const* d_in, const int* in_sizes, int n_in,
                              void* d_out, int out_size) {
    const float* x      = (const float*)d_in[0];
    const float* xc_w   = (const float*)d_in[1];
    const float* dtc_w  = (const float*)d_in[2];
    const float* dtc_b  = (const float*)d_in[3];
    const float* Ac     = (const float*)d_in[4];
    const float* Dcs    = (const float*)d_in[5];
    const float* w_cin  = (const float*)d_in[6];
    const float* bn_g   = (const float*)d_in[7];
    const float* bn_b   = (const float*)d_in[8];
    const float* bn_m   = (const float*)d_in[9];
    const float* bn_v   = (const float*)d_in[10];
    const float* w_cout = (const float*)d_in[11];
    const float* ln_g   = (const float*)d_in[12];
    const float* ln_b   = (const float*)d_in[13];

    pool_kernel<<<B0 * C0, 256>>>(x);
    prep_kernel<<<B0 * 2 * 4, 128>>>(xc_w, dtc_w, dtc_b, w_cin, bn_g, bn_b, bn_m, bn_v);
    scan_kernel<<<256, 128>>>(Ac, Dcs);
    combine_ln_kernel<<<B0, 512>>>(w_cout, ln_g, ln_b);
    out_kernel<<<65536, 256>>>(x, (float*)d_out);
}

// round 2
// speedup vs baseline: 1.0894x; 1.0894x over previous
#include <cuda_runtime.h>
#include <math.h>

#define B0 32
#define C0 512
#define HW 4096
#define DC 32
#define NS 16
#define RK 32
#define LL 512

// ---- global scratch (static device arrays; no runtime malloc) ----
__device__ float g_avg[B0 * C0];
__device__ float g_mx[B0 * C0];
__device__ float g_M[2 * DC * DC];           // fused dtc_w @ xc_w[:RK] per direction
__device__ float g_U[B0 * 2 * DC * LL];      // u layout [bk*32+d][l]
__device__ float g_Delta[B0 * 2 * DC * LL];  // post-softplus delta, same layout
__device__ float g_Bs[B0 * 2 * LL * NS];     // [bk][l][n]
__device__ float g_Cs[B0 * 2 * LL * NS];     // [bk][l][n]
__device__ float g_Y[B0 * 2 * DC * LL];      // scan output, [bk*32+d][l]
__device__ float g_yb[B0 * LL];              // combined gelu(y . w_cout)
__device__ float g_attn[B0 * C0];

__device__ __forceinline__ float gelu_exact(float v) {
    return 0.5f * v * (1.0f + erff(v * 0.70710678118654752f));
}
__device__ __forceinline__ float ex2_fast(float x) {
    float y;
    asm("ex2.approx.ftz.f32 %0, %1;" : "=f"(y) : "f"(x));
    return y;
}

// ============================================================
// K0: fuse weights  M[k][d][dd] = sum_r dtc_w[k][d][r]*xc_w[k][r][dd]
// ============================================================
__global__ void wfuse_kernel(const float* __restrict__ dtc_w,
                             const float* __restrict__ xc_w) {
    const int kd = blockIdx.x;          // 0..63
    const int k = kd >> 5, d = kd & 31;
    const int dd = threadIdx.x;         // 0..31
    float a = 0.0f;
#pragma unroll
    for (int r = 0; r < 32; r++)
        a += dtc_w[k * 1024 + d * 32 + r] * xc_w[k * 2048 + r * 32 + dd];
    g_M[kd * 32 + dd] = a;
}

// ============================================================
// K1: avg + max pool over H*W per (b,c).  256 MB read, HBM-bound.
// ============================================================
__global__ void pool_kernel(const float* __restrict__ x) {
    int bc = blockIdx.x;
    const float4* xp = (const float4*)(x + (size_t)bc * HW);
    float s = 0.0f, m = -INFINITY;
#pragma unroll
    for (int it = 0; it < 4; it++) {
        int i = it * 256 + threadIdx.x;
        float4 v = xp[i];
        s += (v.x + v.y) + (v.z + v.w);
        m = fmaxf(m, fmaxf(fmaxf(v.x, v.y), fmaxf(v.z, v.w)));
    }
#pragma unroll
    for (int o = 16; o; o >>= 1) {
        s += __shfl_xor_sync(0xffffffffu, s, o);
        m = fmaxf(m, __shfl_xor_sync(0xffffffffu, m, o));
    }
    __shared__ float ss[8], sm[8];
    int w = threadIdx.x >> 5;
    if ((threadIdx.x & 31) == 0) { ss[w] = s; sm[w] = m; }
    __syncthreads();
    if (threadIdx.x == 0) {
        float S = ss[0], M = sm[0];
#pragma unroll
        for (int i = 1; i < 8; i++) { S += ss[i]; M = fmaxf(M, sm[i]); }
        g_avg[bc] = S * (1.0f / (float)HW);
        g_mx[bc] = M;
    }
}

// ============================================================
// K2: per (b,k,l): u = gelu(BN(w_cin . xsc)); Bs, Cs projections;
//     delta = softplus(M.u + bias)  (dts intermediate fused into M).
//     grid = B0*2*4 blocks of 128 threads (thread == one l).
// ============================================================
__global__ void prep_kernel(const float* __restrict__ xc_w,
                            const float* __restrict__ dtc_b,
                            const float* __restrict__ w_cin,
                            const float* __restrict__ bn_g,
                            const float* __restrict__ bn_b,
                            const float* __restrict__ bn_m,
                            const float* __restrict__ bn_v) {
    const int bk = blockIdx.x >> 2;        // 0..63
    const int b = bk >> 1, k = bk & 1;
    const int l = ((blockIdx.x & 3) << 7) + threadIdx.x;  // 0..511

    __shared__ float sWbc[32 * 32];  // xc_w rows 32..63 (B then C): [row][d]
    __shared__ float sM[32 * 32];
    __shared__ float sAvg[512], sMx[512];
    __shared__ float sCin0[32], sCin1[32], sScale[32], sShift[32], sBias[32];

    for (int i = threadIdx.x; i < 1024; i += 128) sWbc[i] = xc_w[k * 2048 + 1024 + i];
    for (int i = threadIdx.x; i < 1024; i += 128) sM[i] = g_M[k * 1024 + i];
    for (int i = threadIdx.x; i < 512; i += 128) {
        sAvg[i] = g_avg[b * 512 + i];
        sMx[i] = g_mx[b * 512 + i];
    }
    if (threadIdx.x < 32) {
        int d = threadIdx.x;
        sCin0[d] = w_cin[d * 2 + 0];
        sCin1[d] = w_cin[d * 2 + 1];
        float sc = rsqrtf(bn_v[d] + 1e-5f) * bn_g[d];
        sScale[d] = sc;
        sShift[d] = bn_b[d] - bn_m[d] * sc;
        sBias[d] = dtc_b[k * 32 + d];
    }
    __syncthreads();

    const int c = (k == 0) ? l : (511 - l);
    const float av = sAvg[c], mv = sMx[c];

    float u[32];
#pragma unroll
    for (int d = 0; d < 32; d++) {
        float v = sCin0[d] * av + sCin1[d] * mv;
        v = v * sScale[d] + sShift[d];
        v = gelu_exact(v);
        u[d] = v;
        g_U[(bk * 32 + d) * LL + l] = v;
    }

#pragma unroll
    for (int n = 0; n < 16; n++) {
        float ba = 0.0f, ca = 0.0f;
#pragma unroll
        for (int d = 0; d < 32; d++) {
            ba += u[d] * sWbc[n * 32 + d];
            ca += u[d] * sWbc[(16 + n) * 32 + d];
        }
        g_Bs[(bk * 512 + l) * NS + n] = ba;
        g_Cs[(bk * 512 + l) * NS + n] = ca;
    }
#pragma unroll
    for (int d = 0; d < 32; d++) {
        float a = sBias[d];
#pragma unroll
        for (int dd = 0; dd < 32; dd++) a += u[dd] * sM[d * 32 + dd];
        float sp = fmaxf(a, 0.0f) + log1pf(__expf(-fabsf(a)));  // stable softplus
        g_Delta[(bk * 32 + d) * LL + l] = sp;
    }
}

// ============================================================
// K3: selective scan, chunk=16 restructure.
//     One warp = two (b,k,d) scan lanes; in each 16-lane half,
//     lane n owns state n. Per chunk: batch all loads (MLP 32),
//     folded multi-value butterfly reduction (15 shfl / 16 steps),
//     coalesced y stores.
// ============================================================
__global__ void scan_kernel(const float* __restrict__ Ac_logs,
                            const float* __restrict__ Dcs) {
    const int warp = threadIdx.x >> 5;
    const int lane = threadIdx.x & 31;
    const int half = lane >> 4;
    const int n = lane & 15;
    const int g = blockIdx.x * 8 + warp * 2 + half;  // 0..2047
    const int kd = g & 63;
    const int bkn = g >> 5;

    const float* __restrict__ dp = g_Delta + (size_t)g * LL;
    const float* __restrict__ up = g_U + (size_t)g * LL;
    const float* __restrict__ Bp = g_Bs + (size_t)bkn * (LL * NS) + n;
    const float* __restrict__ Cp = g_Cs + (size_t)bkn * (LL * NS) + n;
    float* __restrict__ yp = g_Y + (size_t)g * LL;

    const float A = -__expf(Ac_logs[kd * NS + n]);
    const float cA = A * 1.4426950408889634f;  // scale for ex2
    const float Dv = Dcs[kd];

    const bool b3 = (n & 8) != 0;
    const bool b2 = (n & 4) != 0;
    const bool b1 = (n & 2) != 0;
    const bool b0 = (n & 1) != 0;

    float h = 0.0f;
    for (int chunk = 0; chunk < 32; chunk++) {
        // --- batched loads for 16 steps ---
        float bv[16], cv[16];
        const float* bc = Bp + chunk * 256;
        const float* cc = Cp + chunk * 256;
#pragma unroll
        for (int j = 0; j < 16; j++) { bv[j] = bc[j * 16]; cv[j] = cc[j * 16]; }
        float dl[16], ul[16];
        const float4* dp4 = (const float4*)(dp + chunk * 16);
        const float4* up4 = (const float4*)(up + chunk * 16);
#pragma unroll
        for (int q = 0; q < 4; q++) {
            float4 t = dp4[q];
            dl[q * 4] = t.x; dl[q * 4 + 1] = t.y; dl[q * 4 + 2] = t.z; dl[q * 4 + 3] = t.w;
            float4 s = up4[q];
            ul[q * 4] = s.x; ul[q * 4 + 1] = s.y; ul[q * 4 + 2] = s.z; ul[q * 4 + 3] = s.w;
        }

        // --- 16 recurrence steps ---
        float v[16];
        float uk = 0.0f;
#pragma unroll
        for (int j = 0; j < 16; j++) {
            const float delta = dl[j];
            const float uu = ul[j];
            const float dA = ex2_fast(delta * cA);
            h = fmaf(dA, h, (delta * uu) * bv[j]);
            v[j] = h * cv[j];
            if (j == n) uk = uu;
        }

        // --- folded butterfly: lane n ends with sum_n' v_n'[n] ---
#pragma unroll
        for (int i = 0; i < 8; i++) {
            float mine = b3 ? v[i + 8] : v[i];
            float oth  = b3 ? v[i]     : v[i + 8];
            v[i] = mine + __shfl_xor_sync(0xffffffffu, oth, 8);
        }
#pragma unroll
        for (int i = 0; i < 4; i++) {
            float mine = b2 ? v[i + 4] : v[i];
            float oth  = b2 ? v[i]     : v[i + 4];
            v[i] = mine + __shfl_xor_sync(0xffffffffu, oth, 4);
        }
#pragma unroll
        for (int i = 0; i < 2; i++) {
            float mine = b1 ? v[i + 2] : v[i];
            float oth  = b1 ? v[i]     : v[i + 2];
            v[i] = mine + __shfl_xor_sync(0xffffffffu, oth, 2);
        }
        {
            float mine = b0 ? v[1] : v[0];
            float oth  = b0 ? v[0] : v[1];
            v[0] = mine + __shfl_xor_sync(0xffffffffu, oth, 1);
        }
        yp[chunk * 16 + n] = v[0] + Dv * uk;
    }
}

// ============================================================
// K4a: yb[b][l] = gelu( sum_d (y0[d,l] + y1[d,511-l]) * w_cout[d] )
//      grid = 128 blocks (b x 4 l-chunks), 128 threads.
// ============================================================
__global__ void yb_kernel(const float* __restrict__ w_cout) {
    const int b = blockIdx.x >> 2;
    const int l = ((blockIdx.x & 3) << 7) + threadIdx.x;
    __shared__ float sw[32];
    if (threadIdx.x < 32) sw[threadIdx.x] = w_cout[threadIdx.x];
    __syncthreads();

    const float* __restrict__ y0 = g_Y + (size_t)b * 64 * LL;
    const float* __restrict__ y1 = y0 + 32 * LL;
    float a0 = 0.0f, a1 = 0.0f, a2 = 0.0f, a3 = 0.0f;
#pragma unroll
    for (int d = 0; d < 32; d += 4) {
        a0 += (y0[(d + 0) * LL + l] + y1[(d + 0) * LL + (511 - l)]) * sw[d + 0];
        a1 += (y0[(d + 1) * LL + l] + y1[(d + 1) * LL + (511 - l)]) * sw[d + 1];
        a2 += (y0[(d + 2) * LL + l] + y1[(d + 2) * LL + (511 - l)]) * sw[d + 2];
        a3 += (y0[(d + 3) * LL + l] + y1[(d + 3) * LL + (511 - l)]) * sw[d + 3];
    }
    g_yb[b * 512 + l] = gelu_exact((a0 + a1) + (a2 + a3));
}

// ============================================================
// K4b: LayerNorm over L per batch -> attn. 64 KB total, fast.
// ============================================================
__global__ void ln_kernel(const float* __restrict__ ln_g,
                          const float* __restrict__ ln_b) {
    const int b = blockIdx.x;
    const int l = threadIdx.x;
    const float yb = g_yb[b * 512 + l];
    float s = yb, s2 = yb * yb;
#pragma unroll
    for (int o = 16; o; o >>= 1) {
        s += __shfl_xor_sync(0xffffffffu, s, o);
        s2 += __shfl_xor_sync(0xffffffffu, s2, o);
    }
    __shared__ float rs[16], rs2[16];
    __shared__ float smu, srv;
    const int w = l >> 5;
    if ((l & 31) == 0) { rs[w] = s; rs2[w] = s2; }
    __syncthreads();
    if (l == 0) {
        float S = 0.0f, S2 = 0.0f;
#pragma unroll
        for (int i = 0; i < 16; i++) { S += rs[i]; S2 += rs2[i]; }
        float mu = S * (1.0f / 512.0f);
        float var = S2 * (1.0f / 512.0f) - mu * mu;
        smu = mu;
        srv = rsqrtf(var + 1e-5f);
    }
    __syncthreads();
    g_attn[b * 512 + l] = (yb - smu) * srv * ln_g[l] + ln_b[l];
}

// ============================================================
// K5: out = x * (1 + attn[b,c]).  512 MB traffic, HBM-bound.
// ============================================================
__global__ void out_kernel(const float* __restrict__ x, float* __restrict__ out) {
    const size_t i = (size_t)blockIdx.x * blockDim.x + threadIdx.x;  // float4 index
    const int bc = (int)(i >> 10);  // 1024 float4 per (b,c)
    const float a = 1.0f + g_attn[bc];
    float4 v = ((const float4*)x)[i];
    v.x *= a; v.y *= a; v.z *= a; v.w *= a;
    ((float4*)out)[i] = v;
}

extern "C" void kernel_launch(void* const* d_in, const int* in_sizes, int n_in,
                              void* d_out, int out_size) {
    const float* x      = (const float*)d_in[0];
    const float* xc_w   = (const float*)d_in[1];
    const float* dtc_w  = (const float*)d_in[2];
    const float* dtc_b  = (const float*)d_in[3];
    const float* Ac     = (const float*)d_in[4];
    const float* Dcs    = (const float*)d_in[5];
    const float* w_cin  = (const float*)d_in[6];
    const float* bn_g   = (const float*)d_in[7];
    const float* bn_b   = (const float*)d_in[8];
    const float* bn_m   = (const float*)d_in[9];
    const float* bn_v   = (const float*)d_in[10];
    const float* w_cout = (const float*)d_in[11];
    const float* ln_g   = (const float*)d_in[12];
    const float* ln_b   = (const float*)d_in[13];

    wfuse_kernel<<<64, 32>>>(dtc_w, xc_w);
    pool_kernel<<<B0 * C0, 256>>>(x);
    prep_kernel<<<B0 * 2 * 4, 128>>>(xc_w, dtc_b, w_cin, bn_g, bn_b, bn_m, bn_v);
    scan_kernel<<<256, 128>>>(Ac, Dcs);
    yb_kernel<<<B0 * 4, 128>>>(w_cout);
    ln_kernel<<<B0, 512>>>(ln_g, ln_b);
    out_kernel<<<65536, 256>>>(x, (float*)d_out);
}

// round 3
// speedup vs baseline: 1.3095x; 1.2021x over previous
#include <cuda_runtime.h>
#include <math.h>

#define B0 32
#define C0 512
#define HW 4096
#define DC 32
#define NS 16
#define RK 32
#define LL 512

// ---- global scratch (static device arrays; no runtime malloc) ----
__device__ float g_avg[B0 * C0];
__device__ float g_mx[B0 * C0];
__device__ float g_M[2 * DC * DC];           // fused dtc_w @ xc_w[:RK] per direction
__device__ float g_U[B0 * 2 * DC * LL];      // u layout [bk*32+d][l]
__device__ float g_Delta[B0 * 2 * DC * LL];  // post-softplus delta, same layout
__device__ float g_Bs[B0 * 2 * LL * NS];     // [bk][l][n]
__device__ float g_Cs[B0 * 2 * LL * NS];     // [bk][l][n]
__device__ float g_Y[B0 * 2 * DC * LL];      // scan output, [bk*32+d][l]
__device__ float g_yb[B0 * LL];              // combined gelu(y . w_cout)
__device__ float g_attn[B0 * C0];

__device__ __forceinline__ float gelu_exact(float v) {
    return 0.5f * v * (1.0f + erff(v * 0.70710678118654752f));
}
__device__ __forceinline__ float ex2_fast(float x) {
    float y;
    asm("ex2.approx.ftz.f32 %0, %1;" : "=f"(y) : "f"(x));
    return y;
}

// ============================================================
// K0: fuse weights  M[k][d][dd] = sum_r dtc_w[k][d][r]*xc_w[k][r][dd]
// ============================================================
__global__ void wfuse_kernel(const float* __restrict__ dtc_w,
                             const float* __restrict__ xc_w) {
    const int kd = blockIdx.x;          // 0..63
    const int k = kd >> 5, d = kd & 31;
    const int dd = threadIdx.x;         // 0..31
    float a = 0.0f;
#pragma unroll
    for (int r = 0; r < 32; r++)
        a += dtc_w[k * 1024 + d * 32 + r] * xc_w[k * 2048 + r * 32 + dd];
    g_M[kd * 32 + dd] = a;
}

// ============================================================
// K1: avg + max pool over H*W per (b,c).  256 MB read, HBM-bound.
// ============================================================
__global__ void pool_kernel(const float* __restrict__ x) {
    int bc = blockIdx.x;
    const float4* xp = (const float4*)(x + (size_t)bc * HW);
    float s = 0.0f, m = -INFINITY;
#pragma unroll
    for (int it = 0; it < 4; it++) {
        int i = it * 256 + threadIdx.x;
        float4 v = xp[i];
        s += (v.x + v.y) + (v.z + v.w);
        m = fmaxf(m, fmaxf(fmaxf(v.x, v.y), fmaxf(v.z, v.w)));
    }
#pragma unroll
    for (int o = 16; o; o >>= 1) {
        s += __shfl_xor_sync(0xffffffffu, s, o);
        m = fmaxf(m, __shfl_xor_sync(0xffffffffu, m, o));
    }
    __shared__ float ss[8], sm[8];
    int w = threadIdx.x >> 5;
    if ((threadIdx.x & 31) == 0) { ss[w] = s; sm[w] = m; }
    __syncthreads();
    if (threadIdx.x == 0) {
        float S = ss[0], M = sm[0];
#pragma unroll
        for (int i = 1; i < 8; i++) { S += ss[i]; M = fmaxf(M, sm[i]); }
        g_avg[bc] = S * (1.0f / (float)HW);
        g_mx[bc] = M;
    }
}

// ============================================================
// K2: per (b,k,l): u = gelu(BN(w_cin . xsc)); Bs, Cs projections;
//     delta = softplus(M.u + bias).
// ============================================================
__global__ void prep_kernel(const float* __restrict__ xc_w,
                            const float* __restrict__ dtc_b,
                            const float* __restrict__ w_cin,
                            const float* __restrict__ bn_g,
                            const float* __restrict__ bn_b,
                            const float* __restrict__ bn_m,
                            const float* __restrict__ bn_v) {
    const int bk = blockIdx.x >> 2;        // 0..63
    const int b = bk >> 1, k = bk & 1;
    const int l = ((blockIdx.x & 3) << 7) + threadIdx.x;  // 0..511

    __shared__ float sWbc[32 * 32];  // xc_w rows 32..63 (B then C): [row][d]
    __shared__ float sM[32 * 32];
    __shared__ float sAvg[512], sMx[512];
    __shared__ float sCin0[32], sCin1[32], sScale[32], sShift[32], sBias[32];

    for (int i = threadIdx.x; i < 1024; i += 128) sWbc[i] = xc_w[k * 2048 + 1024 + i];
    for (int i = threadIdx.x; i < 1024; i += 128) sM[i] = g_M[k * 1024 + i];
    for (int i = threadIdx.x; i < 512; i += 128) {
        sAvg[i] = g_avg[b * 512 + i];
        sMx[i] = g_mx[b * 512 + i];
    }
    if (threadIdx.x < 32) {
        int d = threadIdx.x;
        sCin0[d] = w_cin[d * 2 + 0];
        sCin1[d] = w_cin[d * 2 + 1];
        float sc = rsqrtf(bn_v[d] + 1e-5f) * bn_g[d];
        sScale[d] = sc;
        sShift[d] = bn_b[d] - bn_m[d] * sc;
        sBias[d] = dtc_b[k * 32 + d];
    }
    __syncthreads();

    const int c = (k == 0) ? l : (511 - l);
    const float av = sAvg[c], mv = sMx[c];

    float u[32];
#pragma unroll
    for (int d = 0; d < 32; d++) {
        float v = sCin0[d] * av + sCin1[d] * mv;
        v = v * sScale[d] + sShift[d];
        v = gelu_exact(v);
        u[d] = v;
        g_U[(bk * 32 + d) * LL + l] = v;
    }

#pragma unroll
    for (int n = 0; n < 16; n++) {
        float ba = 0.0f, ca = 0.0f;
#pragma unroll
        for (int d = 0; d < 32; d++) {
            ba += u[d] * sWbc[n * 32 + d];
            ca += u[d] * sWbc[(16 + n) * 32 + d];
        }
        g_Bs[(bk * 512 + l) * NS + n] = ba;
        g_Cs[(bk * 512 + l) * NS + n] = ca;
    }
#pragma unroll
    for (int d = 0; d < 32; d++) {
        float a = sBias[d];
#pragma unroll
        for (int dd = 0; dd < 32; dd++) a += u[dd] * sM[d * 32 + dd];
        float sp = fmaxf(a, 0.0f) + log1pf(__expf(-fabsf(a)));  // stable softplus
        g_Delta[(bk * 32 + d) * LL + l] = sp;
    }
}

// ============================================================
// K3: selective scan, chunk=16, spill-free.
//     512 blocks x 64 threads (__launch_bounds__(64,8) -> <=128 regs).
//     One warp = two (b,k,d) lanes; in each 16-lane half, lane n
//     owns state n. Per chunk: batch loads (MLP), transform to
//     dA/dBu (decouple MUFU latency from the h-chain), 16-FMA
//     serial chain, folded butterfly (15 shfl / 16 steps).
// ============================================================
__global__ void __launch_bounds__(64, 8)
scan_kernel(const float* __restrict__ Ac_logs,
            const float* __restrict__ Dcs) {
    const int warp = threadIdx.x >> 5;
    const int lane = threadIdx.x & 31;
    const int half = lane >> 4;
    const int n = lane & 15;
    const int g = blockIdx.x * 4 + warp * 2 + half;  // 0..2047
    const int kd = g & 63;
    const int bkn = g >> 5;

    const float* __restrict__ dp = g_Delta + (size_t)g * LL;
    const float* __restrict__ up = g_U + (size_t)g * LL;
    const float* __restrict__ Bp = g_Bs + (size_t)bkn * (LL * NS) + n;
    const float* __restrict__ Cp = g_Cs + (size_t)bkn * (LL * NS) + n;
    float* __restrict__ yp = g_Y + (size_t)g * LL;

    const float A = -__expf(Ac_logs[kd * NS + n]);
    const float cA = A * 1.4426950408889634f;  // scale for ex2
    const float Dv = Dcs[kd];

    const bool b3 = (n & 8) != 0;
    const bool b2 = (n & 4) != 0;
    const bool b1 = (n & 2) != 0;
    const bool b0 = (n & 1) != 0;

    float h = 0.0f;
    for (int chunk = 0; chunk < 32; chunk++) {
        // --- batched loads for 16 steps (all independent -> high MLP) ---
        float dA[16];   // starts as delta, becomes exp2(delta*cA)
        float dBu[16];  // starts as u, becomes delta*u*B
        float cv[16];
        {
            const float4* dp4 = (const float4*)(dp + chunk * 16);
            const float4* up4 = (const float4*)(up + chunk * 16);
#pragma unroll
            for (int q = 0; q < 4; q++) {
                float4 t = dp4[q];
                dA[q * 4] = t.x; dA[q * 4 + 1] = t.y; dA[q * 4 + 2] = t.z; dA[q * 4 + 3] = t.w;
                float4 s = up4[q];
                dBu[q * 4] = s.x; dBu[q * 4 + 1] = s.y; dBu[q * 4 + 2] = s.z; dBu[q * 4 + 3] = s.w;
            }
        }
        const float uk = dBu[0] * 0.0f + ((const float*)up)[chunk * 16 + n];  // lane's own u
        {
            const float* bc = Bp + chunk * 256;
            const float* cc = Cp + chunk * 256;
#pragma unroll
            for (int j = 0; j < 16; j++) {
                float bvj = bc[j * 16];
                cv[j] = cc[j * 16];
                dBu[j] = dA[j] * dBu[j] * bvj;   // delta * u * B
                dA[j] = ex2_fast(dA[j] * cA);    // exp(delta * A)
            }
        }

        // --- 16-step serial recurrence (pure FMA chain, lat 4/step) ---
        float v[16];
#pragma unroll
        for (int j = 0; j < 16; j++) {
            h = fmaf(dA[j], h, dBu[j]);
            v[j] = h * cv[j];
        }

        // --- folded butterfly: lane n ends with sum over states of v[n] ---
#pragma unroll
        for (int i = 0; i < 8; i++) {
            float mine = b3 ? v[i + 8] : v[i];
            float oth  = b3 ? v[i]     : v[i + 8];
            v[i] = mine + __shfl_xor_sync(0xffffffffu, oth, 8);
        }
#pragma unroll
        for (int i = 0; i < 4; i++) {
            float mine = b2 ? v[i + 4] : v[i];
            float oth  = b2 ? v[i]     : v[i + 4];
            v[i] = mine + __shfl_xor_sync(0xffffffffu, oth, 4);
        }
#pragma unroll
        for (int i = 0; i < 2; i++) {
            float mine = b1 ? v[i + 2] : v[i];
            float oth  = b1 ? v[i]     : v[i + 2];
            v[i] = mine + __shfl_xor_sync(0xffffffffu, oth, 2);
        }
        {
            float mine = b0 ? v[1] : v[0];
            float oth  = b0 ? v[0] : v[1];
            v[0] = mine + __shfl_xor_sync(0xffffffffu, oth, 1);
        }
        yp[chunk * 16 + n] = v[0] + Dv * uk;
    }
}

// ============================================================
// K4a: yb[b][l] = gelu( sum_d (y0[d,l] + y1[d,511-l]) * w_cout[d] )
// ============================================================
__global__ void yb_kernel(const float* __restrict__ w_cout) {
    const int b = blockIdx.x >> 2;
    const int l = ((blockIdx.x & 3) << 7) + threadIdx.x;
    __shared__ float sw[32];
    if (threadIdx.x < 32) sw[threadIdx.x] = w_cout[threadIdx.x];
    __syncthreads();

    const float* __restrict__ y0 = g_Y + (size_t)b * 64 * LL;
    const float* __restrict__ y1 = y0 + 32 * LL;
    float a0 = 0.0f, a1 = 0.0f, a2 = 0.0f, a3 = 0.0f;
#pragma unroll
    for (int d = 0; d < 32; d += 4) {
        a0 += (y0[(d + 0) * LL + l] + y1[(d + 0) * LL + (511 - l)]) * sw[d + 0];
        a1 += (y0[(d + 1) * LL + l] + y1[(d + 1) * LL + (511 - l)]) * sw[d + 1];
        a2 += (y0[(d + 2) * LL + l] + y1[(d + 2) * LL + (511 - l)]) * sw[d + 2];
        a3 += (y0[(d + 3) * LL + l] + y1[(d + 3) * LL + (511 - l)]) * sw[d + 3];
    }
    g_yb[b * 512 + l] = gelu_exact((a0 + a1) + (a2 + a3));
}

// ============================================================
// K4b: LayerNorm over L per batch -> attn.
// ============================================================
__global__ void ln_kernel(const float* __restrict__ ln_g,
                          const float* __restrict__ ln_b) {
    const int b = blockIdx.x;
    const int l = threadIdx.x;
    const float yb = g_yb[b * 512 + l];
    float s = yb, s2 = yb * yb;
#pragma unroll
    for (int o = 16; o; o >>= 1) {
        s += __shfl_xor_sync(0xffffffffu, s, o);
        s2 += __shfl_xor_sync(0xffffffffu, s2, o);
    }
    __shared__ float rs[16], rs2[16];
    __shared__ float smu, srv;
    const int w = l >> 5;
    if ((l & 31) == 0) { rs[w] = s; rs2[w] = s2; }
    __syncthreads();
    if (l == 0) {
        float S = 0.0f, S2 = 0.0f;
#pragma unroll
        for (int i = 0; i < 16; i++) { S += rs[i]; S2 += rs2[i]; }
        float mu = S * (1.0f / 512.0f);
        float var = S2 * (1.0f / 512.0f) - mu * mu;
        smu = mu;
        srv = rsqrtf(var + 1e-5f);
    }
    __syncthreads();
    g_attn[b * 512 + l] = (yb - smu) * srv * ln_g[l] + ln_b[l];
}

// ============================================================
// K5: out = x * (1 + attn[b,c]).  512 MB traffic, HBM-bound.
// ============================================================
__global__ void out_kernel(const float* __restrict__ x, float* __restrict__ out) {
    const size_t i = (size_t)blockIdx.x * blockDim.x + threadIdx.x;  // float4 index
    const int bc = (int)(i >> 10);  // 1024 float4 per (b,c)
    const float a = 1.0f + g_attn[bc];
    float4 v = ((const float4*)x)[i];
    v.x *= a; v.y *= a; v.z *= a; v.w *= a;
    ((float4*)out)[i] = v;
}

extern "C" void kernel_launch(void* const* d_in, const int* in_sizes, int n_in,
                              void* d_out, int out_size) {
    const float* x      = (const float*)d_in[0];
    const float* xc_w   = (const float*)d_in[1];
    const float* dtc_w  = (const float*)d_in[2];
    const float* dtc_b  = (const float*)d_in[3];
    const float* Ac     = (const float*)d_in[4];
    const float* Dcs    = (const float*)d_in[5];
    const float* w_cin  = (const float*)d_in[6];
    const float* bn_g   = (const float*)d_in[7];
    const float* bn_b   = (const float*)d_in[8];
    const float* bn_m   = (const float*)d_in[9];
    const float* bn_v   = (const float*)d_in[10];
    const float* w_cout = (const float*)d_in[11];
    const float* ln_g   = (const float*)d_in[12];
    const float* ln_b   = (const float*)d_in[13];

    wfuse_kernel<<<64, 32>>>(dtc_w, xc_w);
    pool_kernel<<<B0 * C0, 256>>>(x);
    prep_kernel<<<B0 * 2 * 4, 128>>>(xc_w, dtc_b, w_cin, bn_g, bn_b, bn_m, bn_v);
    scan_kernel<<<512, 64>>>(Ac, Dcs);
    yb_kernel<<<B0 * 4, 128>>>(w_cout);
    ln_kernel<<<B0, 512>>>(ln_g, ln_b);
    out_kernel<<<65536, 256>>>(x, (float*)d_out);
}

// round 4
// speedup vs baseline: 1.3366x; 1.0207x over previous
#include <cuda_runtime.h>
#include <math.h>

#define B0 32
#define C0 512
#define HW 4096
#define DC 32
#define NS 16
#define RK 32
#define LL 512

// ---- global scratch (static device arrays; no runtime malloc) ----
__device__ float g_avg[B0 * C0];
__device__ float g_mx[B0 * C0];
__device__ float g_M[2 * DC * DC];           // fused dtc_w @ xc_w[:RK] per direction
__device__ float g_U[B0 * 2 * DC * LL];      // u layout [bk*32+d][l]
__device__ float g_Delta[B0 * 2 * DC * LL];  // post-softplus delta, same layout
__device__ float g_Bs[B0 * 2 * LL * NS];     // [bk][l][n]
__device__ float g_Cs[B0 * 2 * LL * NS];     // [bk][l][n]
__device__ float g_Y[B0 * 2 * DC * LL];      // scan output, [bk*32+d][l]
__device__ float g_yb[B0 * LL];              // combined gelu(y . w_cout)
__device__ float g_attn[B0 * C0];

__device__ __forceinline__ float gelu_exact(float v) {
    return 0.5f * v * (1.0f + erff(v * 0.70710678118654752f));
}
__device__ __forceinline__ float ex2_fast(float x) {
    float y;
    asm("ex2.approx.ftz.f32 %0, %1;" : "=f"(y) : "f"(x));
    return y;
}

// ============================================================
// K0: fuse weights  M[k][d][dd] = sum_r dtc_w[k][d][r]*xc_w[k][r][dd]
// ============================================================
__global__ void wfuse_kernel(const float* __restrict__ dtc_w,
                             const float* __restrict__ xc_w) {
    const int kd = blockIdx.x;          // 0..63
    const int k = kd >> 5, d = kd & 31;
    const int dd = threadIdx.x;         // 0..31
    float a = 0.0f;
#pragma unroll
    for (int r = 0; r < 32; r++)
        a += dtc_w[k * 1024 + d * 32 + r] * xc_w[k * 2048 + r * 32 + dd];
    g_M[kd * 32 + dd] = a;
}

// ============================================================
// K1: avg + max pool over H*W per (b,c).  256 MB read, HBM-bound.
// ============================================================
__global__ void pool_kernel(const float* __restrict__ x) {
    int bc = blockIdx.x;
    const float4* xp = (const float4*)(x + (size_t)bc * HW);
    float s = 0.0f, m = -INFINITY;
#pragma unroll
    for (int it = 0; it < 4; it++) {
        int i = it * 256 + threadIdx.x;
        float4 v = xp[i];
        s += (v.x + v.y) + (v.z + v.w);
        m = fmaxf(m, fmaxf(fmaxf(v.x, v.y), fmaxf(v.z, v.w)));
    }
#pragma unroll
    for (int o = 16; o; o >>= 1) {
        s += __shfl_xor_sync(0xffffffffu, s, o);
        m = fmaxf(m, __shfl_xor_sync(0xffffffffu, m, o));
    }
    __shared__ float ss[8], sm[8];
    int w = threadIdx.x >> 5;
    if ((threadIdx.x & 31) == 0) { ss[w] = s; sm[w] = m; }
    __syncthreads();
    if (threadIdx.x == 0) {
        float S = ss[0], M = sm[0];
#pragma unroll
        for (int i = 1; i < 8; i++) { S += ss[i]; M = fmaxf(M, sm[i]); }
        g_avg[bc] = S * (1.0f / (float)HW);
        g_mx[bc] = M;
    }
}

// ============================================================
// K2: per (b,k,l): u = gelu(BN(w_cin . xsc)); Bs, Cs projections;
//     delta = softplus(M.u + bias).
// ============================================================
__global__ void prep_kernel(const float* __restrict__ xc_w,
                            const float* __restrict__ dtc_b,
                            const float* __restrict__ w_cin,
                            const float* __restrict__ bn_g,
                            const float* __restrict__ bn_b,
                            const float* __restrict__ bn_m,
                            const float* __restrict__ bn_v) {
    const int bk = blockIdx.x >> 2;        // 0..63
    const int b = bk >> 1, k = bk & 1;
    const int l = ((blockIdx.x & 3) << 7) + threadIdx.x;  // 0..511

    __shared__ float sWbc[32 * 32];  // xc_w rows 32..63 (B then C): [row][d]
    __shared__ float sM[32 * 32];
    __shared__ float sAvg[512], sMx[512];
    __shared__ float sCin0[32], sCin1[32], sScale[32], sShift[32], sBias[32];

    for (int i = threadIdx.x; i < 1024; i += 128) sWbc[i] = xc_w[k * 2048 + 1024 + i];
    for (int i = threadIdx.x; i < 1024; i += 128) sM[i] = g_M[k * 1024 + i];
    for (int i = threadIdx.x; i < 512; i += 128) {
        sAvg[i] = g_avg[b * 512 + i];
        sMx[i] = g_mx[b * 512 + i];
    }
    if (threadIdx.x < 32) {
        int d = threadIdx.x;
        sCin0[d] = w_cin[d * 2 + 0];
        sCin1[d] = w_cin[d * 2 + 1];
        float sc = rsqrtf(bn_v[d] + 1e-5f) * bn_g[d];
        sScale[d] = sc;
        sShift[d] = bn_b[d] - bn_m[d] * sc;
        sBias[d] = dtc_b[k * 32 + d];
    }
    __syncthreads();

    const int c = (k == 0) ? l : (511 - l);
    const float av = sAvg[c], mv = sMx[c];

    float u[32];
#pragma unroll
    for (int d = 0; d < 32; d++) {
        float v = sCin0[d] * av + sCin1[d] * mv;
        v = v * sScale[d] + sShift[d];
        v = gelu_exact(v);
        u[d] = v;
        g_U[(bk * 32 + d) * LL + l] = v;
    }

#pragma unroll
    for (int n = 0; n < 16; n++) {
        float ba = 0.0f, ca = 0.0f;
#pragma unroll
        for (int d = 0; d < 32; d++) {
            ba += u[d] * sWbc[n * 32 + d];
            ca += u[d] * sWbc[(16 + n) * 32 + d];
        }
        g_Bs[(bk * 512 + l) * NS + n] = ba;
        g_Cs[(bk * 512 + l) * NS + n] = ca;
    }
#pragma unroll
    for (int d = 0; d < 32; d++) {
        float a = sBias[d];
#pragma unroll
        for (int dd = 0; dd < 32; dd++) a += u[dd] * sM[d * 32 + dd];
        float sp = fmaxf(a, 0.0f) + log1pf(__expf(-fabsf(a)));  // stable softplus
        g_Delta[(bk * 32 + d) * LL + l] = sp;
    }
}

// ============================================================
// K3: selective scan, chunk=16, double-buffered (software pipeline).
//     512 blocks x 64 threads, __launch_bounds__(64,4) -> <=256 regs.
//     One warp = two (b,k,d) lanes; lane n owns state n within a half.
//     Loads for chunk c+1 are issued before computing chunk c, so the
//     ~250-cycle L2 latency overlaps the FMA chain + butterfly.
// ============================================================
struct ChunkBuf {
    float dl[16], ul[16], bv[16], cv[16], uk;
};

__device__ __forceinline__ void load_chunk(int chunk, int n,
                                           const float* __restrict__ dp,
                                           const float* __restrict__ up,
                                           const float* __restrict__ Bp,
                                           const float* __restrict__ Cp,
                                           ChunkBuf& t) {
    const float4* dp4 = (const float4*)(dp + chunk * 16);
    const float4* up4 = (const float4*)(up + chunk * 16);
#pragma unroll
    for (int q = 0; q < 4; q++) {
        float4 a = dp4[q];
        t.dl[q * 4] = a.x; t.dl[q * 4 + 1] = a.y; t.dl[q * 4 + 2] = a.z; t.dl[q * 4 + 3] = a.w;
        float4 s = up4[q];
        t.ul[q * 4] = s.x; t.ul[q * 4 + 1] = s.y; t.ul[q * 4 + 2] = s.z; t.ul[q * 4 + 3] = s.w;
    }
    const float* bc = Bp + chunk * 256;
    const float* cc = Cp + chunk * 256;
#pragma unroll
    for (int j = 0; j < 16; j++) { t.bv[j] = bc[j * 16]; t.cv[j] = cc[j * 16]; }
    t.uk = up[chunk * 16 + n];
}

__device__ __forceinline__ void compute_chunk(int chunk, int n, float cA, float Dv,
                                              bool b3, bool b2, bool b1, bool b0,
                                              float& h, float* __restrict__ yp,
                                              ChunkBuf& t) {
    // transform (independent ops; overlaps MUFU latency)
#pragma unroll
    for (int j = 0; j < 16; j++) {
        t.ul[j] = t.dl[j] * t.ul[j] * t.bv[j];  // delta*u*B
        t.dl[j] = ex2_fast(t.dl[j] * cA);       // exp(delta*A)
    }
    // serial recurrence; v written in place of cv
#pragma unroll
    for (int j = 0; j < 16; j++) {
        h = fmaf(t.dl[j], h, t.ul[j]);
        t.cv[j] = h * t.cv[j];
    }
    // folded butterfly: lane n ends with sum over states of value at l=n
#pragma unroll
    for (int i = 0; i < 8; i++) {
        float mine = b3 ? t.cv[i + 8] : t.cv[i];
        float oth  = b3 ? t.cv[i]     : t.cv[i + 8];
        t.cv[i] = mine + __shfl_xor_sync(0xffffffffu, oth, 8);
    }
#pragma unroll
    for (int i = 0; i < 4; i++) {
        float mine = b2 ? t.cv[i + 4] : t.cv[i];
        float oth  = b2 ? t.cv[i]     : t.cv[i + 4];
        t.cv[i] = mine + __shfl_xor_sync(0xffffffffu, oth, 4);
    }
#pragma unroll
    for (int i = 0; i < 2; i++) {
        float mine = b1 ? t.cv[i + 2] : t.cv[i];
        float oth  = b1 ? t.cv[i]     : t.cv[i + 2];
        t.cv[i] = mine + __shfl_xor_sync(0xffffffffu, oth, 2);
    }
    {
        float mine = b0 ? t.cv[1] : t.cv[0];
        float oth  = b0 ? t.cv[0] : t.cv[1];
        t.cv[0] = mine + __shfl_xor_sync(0xffffffffu, oth, 1);
    }
    yp[chunk * 16 + n] = t.cv[0] + Dv * t.uk;
}

__global__ void __launch_bounds__(64, 4)
scan_kernel(const float* __restrict__ Ac_logs,
            const float* __restrict__ Dcs) {
    const int warp = threadIdx.x >> 5;
    const int lane = threadIdx.x & 31;
    const int half = lane >> 4;
    const int n = lane & 15;
    const int g = blockIdx.x * 4 + warp * 2 + half;  // 0..2047
    const int kd = g & 63;
    const int bkn = g >> 5;

    const float* __restrict__ dp = g_Delta + (size_t)g * LL;
    const float* __restrict__ up = g_U + (size_t)g * LL;
    const float* __restrict__ Bp = g_Bs + (size_t)bkn * (LL * NS) + n;
    const float* __restrict__ Cp = g_Cs + (size_t)bkn * (LL * NS) + n;
    float* __restrict__ yp = g_Y + (size_t)g * LL;

    const float A = -__expf(Ac_logs[kd * NS + n]);
    const float cA = A * 1.4426950408889634f;  // scale for ex2
    const float Dv = Dcs[kd];

    const bool b3 = (n & 8) != 0;
    const bool b2 = (n & 4) != 0;
    const bool b1 = (n & 2) != 0;
    const bool b0 = (n & 1) != 0;

    ChunkBuf buf0, buf1;
    float h = 0.0f;

    load_chunk(0, n, dp, up, Bp, Cp, buf0);
#pragma unroll 1
    for (int c = 0; c < 32; c += 2) {
        load_chunk(c + 1, n, dp, up, Bp, Cp, buf1);
        compute_chunk(c, n, cA, Dv, b3, b2, b1, b0, h, yp, buf0);
        if (c + 2 < 32) load_chunk(c + 2, n, dp, up, Bp, Cp, buf0);
        compute_chunk(c + 1, n, cA, Dv, b3, b2, b1, b0, h, yp, buf1);
    }
}

// ============================================================
// K4a: yb[b][l] = gelu( sum_d (y0[d,l] + y1[d,511-l]) * w_cout[d] )
// ============================================================
__global__ void yb_kernel(const float* __restrict__ w_cout) {
    const int b = blockIdx.x >> 2;
    const int l = ((blockIdx.x & 3) << 7) + threadIdx.x;
    __shared__ float sw[32];
    if (threadIdx.x < 32) sw[threadIdx.x] = w_cout[threadIdx.x];
    __syncthreads();

    const float* __restrict__ y0 = g_Y + (size_t)b * 64 * LL;
    const float* __restrict__ y1 = y0 + 32 * LL;
    float a0 = 0.0f, a1 = 0.0f, a2 = 0.0f, a3 = 0.0f;
#pragma unroll
    for (int d = 0; d < 32; d += 4) {
        a0 += (y0[(d + 0) * LL + l] + y1[(d + 0) * LL + (511 - l)]) * sw[d + 0];
        a1 += (y0[(d + 1) * LL + l] + y1[(d + 1) * LL + (511 - l)]) * sw[d + 1];
        a2 += (y0[(d + 2) * LL + l] + y1[(d + 2) * LL + (511 - l)]) * sw[d + 2];
        a3 += (y0[(d + 3) * LL + l] + y1[(d + 3) * LL + (511 - l)]) * sw[d + 3];
    }
    g_yb[b * 512 + l] = gelu_exact((a0 + a1) + (a2 + a3));
}

// ============================================================
// K4b: LayerNorm over L per batch -> attn.
// ============================================================
__global__ void ln_kernel(const float* __restrict__ ln_g,
                          const float* __restrict__ ln_b) {
    const int b = blockIdx.x;
    const int l = threadIdx.x;
    const float yb = g_yb[b * 512 + l];
    float s = yb, s2 = yb * yb;
#pragma unroll
    for (int o = 16; o; o >>= 1) {
        s += __shfl_xor_sync(0xffffffffu, s, o);
        s2 += __shfl_xor_sync(0xffffffffu, s2, o);
    }
    __shared__ float rs[16], rs2[16];
    __shared__ float smu, srv;
    const int w = l >> 5;
    if ((l & 31) == 0) { rs[w] = s; rs2[w] = s2; }
    __syncthreads();
    if (l == 0) {
        float S = 0.0f, S2 = 0.0f;
#pragma unroll
        for (int i = 0; i < 16; i++) { S += rs[i]; S2 += rs2[i]; }
        float mu = S * (1.0f / 512.0f);
        float var = S2 * (1.0f / 512.0f) - mu * mu;
        smu = mu;
        srv = rsqrtf(var + 1e-5f);
    }
    __syncthreads();
    g_attn[b * 512 + l] = (yb - smu) * srv * ln_g[l] + ln_b[l];
}

// ============================================================
// K5: out = x * (1 + attn[b,c]).  512 MB traffic, HBM-bound.
// ============================================================
__global__ void out_kernel(const float* __restrict__ x, float* __restrict__ out) {
    const size_t i = (size_t)blockIdx.x * blockDim.x + threadIdx.x;  // float4 index
    const int bc = (int)(i >> 10);  // 1024 float4 per (b,c)
    const float a = 1.0f + g_attn[bc];
    float4 v = ((const float4*)x)[i];
    v.x *= a; v.y *= a; v.z *= a; v.w *= a;
    ((float4*)out)[i] = v;
}

extern "C" void kernel_launch(void* const* d_in, const int* in_sizes, int n_in,
                              void* d_out, int out_size) {
    const float* x      = (const float*)d_in[0];
    const float* xc_w   = (const float*)d_in[1];
    const float* dtc_w  = (const float*)d_in[2];
    const float* dtc_b  = (const float*)d_in[3];
    const float* Ac     = (const float*)d_in[4];
    const float* Dcs    = (const float*)d_in[5];
    const float* w_cin  = (const float*)d_in[6];
    const float* bn_g   = (const float*)d_in[7];
    const float* bn_b   = (const float*)d_in[8];
    const float* bn_m   = (const float*)d_in[9];
    const float* bn_v   = (const float*)d_in[10];
    const float* w_cout = (const float*)d_in[11];
    const float* ln_g   = (const float*)d_in[12];
    const float* ln_b   = (const float*)d_in[13];

    wfuse_kernel<<<64, 32>>>(dtc_w, xc_w);
    pool_kernel<<<B0 * C0, 256>>>(x);
    prep_kernel<<<B0 * 2 * 4, 128>>>(xc_w, dtc_b, w_cin, bn_g, bn_b, bn_m, bn_v);
    scan_kernel<<<512, 64>>>(Ac, Dcs);
    yb_kernel<<<B0 * 4, 128>>>(w_cout);
    ln_kernel<<<B0, 512>>>(ln_g, ln_b);
    out_kernel<<<65536, 256>>>(x, (float*)d_out);
}